// round 5
// baseline (speedup 1.0000x reference)
#include <cuda_runtime.h>
#include <cstdint>
#include <cstddef>

typedef unsigned long long ull;
#define DI __device__ __forceinline__

DI ull pack2(float x, float y){ ull r; asm("mov.b64 %0,{%1,%2};":"=l"(r):"f"(x),"f"(y)); return r; }
DI float2 unp2(ull v){ float2 r; asm("mov.b64 {%0,%1},%2;":"=f"(r.x),"=f"(r.y):"l"(v)); return r; }
DI ull fma2(ull a, ull b, ull c){ ull d; asm("fma.rn.f32x2 %0,%1,%2,%3;":"=l"(d):"l"(a),"l"(b),"l"(c)); return d; }
DI ull mul2(ull a, ull b){ ull d; asm("mul.rn.f32x2 %0,%1,%2;":"=l"(d):"l"(a),"l"(b)); return d; }

constexpr int B_ = 2, S_ = 512, H_ = 8, D_ = 32, DM_ = 256;
constexpr int M_ = B_ * S_;   // 1024 token rows

// Scratch (cudaMalloc forbidden)
__device__ float g_q [M_ * DM_];
__device__ float g_k [M_ * DM_];
__device__ float g_v [M_ * DM_];
__device__ float g_ao[M_ * DM_];

// ---------------------------------------------------------------------------
// Kernel 1: QKV projections. out[m][n] = sum_k x[m][k] * w[k][n]
// grid (4 n-tiles, 16 m-tiles, 3 matrices), 256 threads, 64x64 tile, K-step 32
// ---------------------------------------------------------------------------
__global__ void __launch_bounds__(256) qkv_k(const float* __restrict__ x,
                                             const float* __restrict__ wq,
                                             const float* __restrict__ wk,
                                             const float* __restrict__ wv)
{
    __shared__ float As[64][36];   // [m][k] padded
    __shared__ float Bs[32][64];   // [k][n]
    const int bz = blockIdx.z;
    const float* w = (bz == 0) ? wq : ((bz == 1) ? wk : wv);
    float* out = (bz == 0) ? g_q : ((bz == 1) ? g_k : g_v);
    const int m0 = blockIdx.y * 64, n0 = blockIdx.x * 64;
    const int tid = threadIdx.x, tx = tid & 15, ty = tid >> 4;

    ull acc[4][2];
    #pragma unroll
    for (int r = 0; r < 4; r++) { acc[r][0] = 0ull; acc[r][1] = 0ull; }

    for (int k0 = 0; k0 < DM_; k0 += 32) {
        #pragma unroll
        for (int r = 0; r < 4; r++) {            // A tile: 64x32 = 1024 float2
            int f = r * 256 + tid;
            int row = f >> 4, c2 = f & 15;
            float2 v = *(const float2*)(x + (size_t)(m0 + row) * DM_ + k0 + c2 * 2);
            *(float2*)&As[row][c2 * 2] = v;
        }
        #pragma unroll
        for (int r = 0; r < 4; r++) {            // B tile: 32x64 = 1024 float2
            int f = r * 256 + tid;
            int kk = f >> 5, c2 = f & 31;
            float2 v = *(const float2*)(w + (size_t)(k0 + kk) * DM_ + n0 + c2 * 2);
            *(float2*)&Bs[kk][c2 * 2] = v;
        }
        __syncthreads();
        #pragma unroll
        for (int k = 0; k < 32; k++) {
            ulonglong2 b2 = *(const ulonglong2*)&Bs[k][tx * 4];
            #pragma unroll
            for (int r = 0; r < 4; r++) {
                float a = As[ty * 4 + r][k];
                ull ap = pack2(a, a);
                acc[r][0] = fma2(ap, b2.x, acc[r][0]);
                acc[r][1] = fma2(ap, b2.y, acc[r][1]);
            }
        }
        __syncthreads();
    }
    #pragma unroll
    for (int r = 0; r < 4; r++) {
        float2 lo = unp2(acc[r][0]), hi = unp2(acc[r][1]);
        float4 o; o.x = lo.x; o.y = lo.y; o.z = hi.x; o.w = hi.y;
        *(float4*)(out + (size_t)(m0 + ty * 4 + r) * DM_ + n0 + tx * 4) = o;
    }
}

// ---------------------------------------------------------------------------
// Kernel 2: attention. Block = (b, 4 query rows i, all 8 heads). 256 threads.
// scores[b,h,i,j] = sum_d q[b,h,j,d] * k[b,h,i,d] * rpe[b,i,j,d] / sqrt(D)
// mask: j < station_num OR j == i; softmax over j; out = attn @ v
// ---------------------------------------------------------------------------
constexpr int QV_ST = 258;                    // 32 x 258 staging (q, then v)
constexpr int OFF_QV  = 0;
constexpr int OFF_RPE = OFF_QV + 32 * QV_ST;          // rpe [4][32][34] (i,d,j)
constexpr int OFF_K   = OFF_RPE + 4 * 32 * 34;        // k   [4][258]
constexpr int OFF_SC  = OFF_K + 4 * 258;              // sc  [32][258] (4i x 8h rows)
constexpr int SMEM_FLOATS = OFF_SC + 32 * 258;
constexpr int SMEM_BYTES  = SMEM_FLOATS * 4;          // 87,584 B

__global__ void __launch_bounds__(256, 2) attn_k(const float* __restrict__ rpe,
                                                 const int* __restrict__ snp)
{
    extern __shared__ float sm[];
    float* qv = sm + OFF_QV;
    float* rp = sm + OFF_RPE;
    float* ks = sm + OFF_K;
    float* sc = sm + OFF_SC;
    const int tid = threadIdx.x;
    const int b = blockIdx.y, i0 = blockIdx.x * 4;
    int sn = *snp; if (sn > 256) sn = 256; if (sn < 0) sn = 0;
    const int nt = (sn + 31) >> 5;
    const float scale = 0.17677669529663687f;  // 1/sqrt(32)

    // stage k: rows i0..i0+3
    #pragma unroll
    for (int r = 0; r < 2; r++) {
        int f = r * 256 + tid; int row = f >> 7, c2 = f & 127;
        *(float2*)&ks[row * 258 + c2 * 2] =
            *(const float2*)(g_k + (size_t)(b * S_ + i0 + row) * DM_ + c2 * 2);
    }

    const int jp = tid & 15, h = (tid >> 4) & 7, ihalf = tid >> 7;
    const int c0 = h * 32;

    // ---------------- score phase ----------------
    for (int jt = 0; jt < nt; jt++) {
        const int j0 = jt * 32;
        __syncthreads();
        // stage q rows j0..j0+31 -> qv[32][258]
        #pragma unroll
        for (int r = 0; r < 16; r++) {
            int f = r * 256 + tid; int row = f >> 7, c2 = f & 127;
            *(float2*)&qv[row * 258 + c2 * 2] =
                *(const float2*)(g_q + (size_t)(b * S_ + j0 + row) * DM_ + c2 * 2);
        }
        // stage rpe transposed: rp[(i*32+d)*34 + j]
        #pragma unroll
        for (int r = 0; r < 4; r++) {
            int f = r * 256 + tid; int rowi = f >> 3, dq = f & 7;
            int i = rowi >> 5, j = rowi & 31;
            float4 v = *(const float4*)(rpe +
                (((size_t)(b * S_ + i0 + i) * S_ + j0 + j) * D_ + dq * 4));
            rp[(i * 32 + dq * 4 + 0) * 34 + j] = v.x;
            rp[(i * 32 + dq * 4 + 1) * 34 + j] = v.y;
            rp[(i * 32 + dq * 4 + 2) * 34 + j] = v.z;
            rp[(i * 32 + dq * 4 + 3) * 34 + j] = v.w;
        }
        __syncthreads();

        ull acc[2] = {0ull, 0ull};
        for (int dh = 0; dh < 32; dh += 16) {
            ull q2[16];                         // j-pair packed q
            #pragma unroll
            for (int dd = 0; dd < 16; dd += 2) {
                float2 a  = *(const float2*)&qv[(2 * jp)     * 258 + c0 + dh + dd];
                float2 bb = *(const float2*)&qv[(2 * jp + 1) * 258 + c0 + dh + dd];
                q2[dd]     = pack2(a.x, bb.x);
                q2[dd + 1] = pack2(a.y, bb.y);
            }
            #pragma unroll
            for (int ii = 0; ii < 2; ii++) {
                int i = ihalf * 2 + ii;
                #pragma unroll
                for (int dd = 0; dd < 16; dd++) {
                    float kv = ks[i * 258 + c0 + dh + dd];
                    ull rv = *(const ull*)&rp[(i * 32 + dh + dd) * 34 + 2 * jp];
                    acc[ii] = fma2(mul2(q2[dd], pack2(kv, kv)), rv, acc[ii]);
                }
            }
        }
        #pragma unroll
        for (int ii = 0; ii < 2; ii++) {
            int i = ihalf * 2 + ii;
            int j = j0 + 2 * jp;
            ull s2 = mul2(acc[ii], pack2(scale, scale));
            if (j + 1 < sn) {
                *(ull*)&sc[(i * 8 + h) * 258 + j] = s2;
            } else if (j < sn) {
                float2 t = unp2(s2);
                sc[(i * 8 + h) * 258 + j] = t.x;
            }
        }
    }

    // diagonal column (only needed when i >= sn)
    if (tid < 32) {
        int il = tid >> 3, hh = tid & 7, i = i0 + il;
        if (i >= sn) {
            float s = 0.f;
            const float* qrow = g_q + (size_t)(b * S_ + i) * DM_ + hh * 32;
            const float* rrow = rpe + ((size_t)(b * S_ + i) * S_ + i) * D_;
            #pragma unroll
            for (int d = 0; d < 32; d++)
                s += qrow[d] * ks[il * 258 + hh * 32 + d] * rrow[d];
            sc[(il * 8 + hh) * 258 + 256] = s * scale;
        }
    }
    __syncthreads();

    // ---------------- softmax (8 warps x 4 rows) ----------------
    {
        int w = tid >> 5, lane = tid & 31;
        int jmax = nt * 32;
        for (int rr = 0; rr < 4; rr++) {
            int row = w * 4 + rr; int il = row >> 3, hh = row & 7;
            bool hd = (i0 + il) >= sn;
            float* srow = &sc[(il * 8 + hh) * 258];
            float mx = -1e30f;
            for (int jj = lane; jj < sn; jj += 32) mx = fmaxf(mx, srow[jj]);
            if (hd && lane == 0) mx = fmaxf(mx, srow[256]);
            #pragma unroll
            for (int o = 16; o > 0; o >>= 1) mx = fmaxf(mx, __shfl_xor_sync(0xffffffffu, mx, o));
            float sum = 0.f;
            for (int jj = lane; jj < jmax; jj += 32) {
                float p = (jj < sn) ? __expf(srow[jj] - mx) : 0.f;
                srow[jj] = p; sum += p;
            }
            if (hd && lane == 0) { float p = __expf(srow[256] - mx); srow[256] = p; sum += p; }
            #pragma unroll
            for (int o = 16; o > 0; o >>= 1) sum += __shfl_xor_sync(0xffffffffu, sum, o);
            float rn = 1.f / sum;
            for (int jj = lane; jj < jmax; jj += 32) srow[jj] *= rn;
            if (hd && lane == 0) srow[256] *= rn;
        }
    }

    // ---------------- AV phase ----------------
    const int dp = jp;            // same bit layout: (dp, h, ihalf)
    ull av[2] = {0ull, 0ull};
    for (int jt = 0; jt < nt; jt++) {
        int j0 = jt * 32;
        __syncthreads();
        #pragma unroll
        for (int r = 0; r < 16; r++) {          // stage v rows into qv buffer
            int f = r * 256 + tid; int row = f >> 7, c2 = f & 127;
            *(float2*)&qv[row * 258 + c2 * 2] =
                *(const float2*)(g_v + (size_t)(b * S_ + j0 + row) * DM_ + c2 * 2);
        }
        __syncthreads();
        #pragma unroll 4
        for (int j = 0; j < 32; j++) {
            int jg = j0 + j;
            ull v2 = *(const ull*)&qv[j * 258 + c0 + 2 * dp];
            #pragma unroll
            for (int ii = 0; ii < 2; ii++) {
                int i = ihalf * 2 + ii;
                float p = sc[(i * 8 + h) * 258 + jg];
                av[ii] = fma2(pack2(p, p), v2, av[ii]);
            }
        }
    }
    #pragma unroll
    for (int ii = 0; ii < 2; ii++) {
        int i = ihalf * 2 + ii; int ig = i0 + i;
        if (ig >= sn) {
            float p = sc[(i * 8 + h) * 258 + 256];
            float2 vv = *(const float2*)(g_v + (size_t)(b * S_ + ig) * DM_ + c0 + 2 * dp);
            av[ii] = fma2(pack2(p, p), pack2(vv.x, vv.y), av[ii]);
        }
        float2 o = unp2(av[ii]);
        *(float2*)(g_ao + (size_t)(b * S_ + ig) * DM_ + c0 + 2 * dp) = o;
    }
}

// ---------------------------------------------------------------------------
// Kernel 3: epilogue. ctx = ao @ fc_w + fc_b + hs, then layernorm.
// 128 blocks x 256 threads; warp per row, lane covers 8 consecutive cols.
// ---------------------------------------------------------------------------
__global__ void __launch_bounds__(256) epi_k(const float* __restrict__ hs,
                                             const float* __restrict__ fw,
                                             const float* __restrict__ fb,
                                             const float* __restrict__ lw,
                                             const float* __restrict__ lb,
                                             float* __restrict__ out)
{
    __shared__ float ao_s[8][256];
    const int tid = threadIdx.x, w = tid >> 5, lane = tid & 31;
    const int row = blockIdx.x * 8 + w;

    #pragma unroll
    for (int t = 0; t < 4; t++) {
        int c2 = t * 32 + lane;
        *(float2*)&ao_s[w][c2 * 2] = *(const float2*)(g_ao + (size_t)row * DM_ + c2 * 2);
    }
    __syncwarp();

    ull acc2[4] = {0ull, 0ull, 0ull, 0ull};
    const float* wbase = fw + lane * 8;
    #pragma unroll 4
    for (int c = 0; c < DM_; c++) {
        float a = ao_s[w][c];
        ull ap = pack2(a, a);
        ulonglong2 u0 = *(const ulonglong2*)(wbase + (size_t)c * DM_);
        ulonglong2 u1 = *(const ulonglong2*)(wbase + (size_t)c * DM_ + 4);
        acc2[0] = fma2(ap, u0.x, acc2[0]);
        acc2[1] = fma2(ap, u0.y, acc2[1]);
        acc2[2] = fma2(ap, u1.x, acc2[2]);
        acc2[3] = fma2(ap, u1.y, acc2[3]);
    }
    float x[8];
    { float2 t0 = unp2(acc2[0]), t1 = unp2(acc2[1]), t2 = unp2(acc2[2]), t3 = unp2(acc2[3]);
      x[0]=t0.x; x[1]=t0.y; x[2]=t1.x; x[3]=t1.y; x[4]=t2.x; x[5]=t2.y; x[6]=t3.x; x[7]=t3.y; }
    const int cb = lane * 8;
    #pragma unroll
    for (int k = 0; k < 8; k++)
        x[k] += fb[cb + k] + hs[(size_t)row * DM_ + cb + k];

    float s = 0.f;
    #pragma unroll
    for (int k = 0; k < 8; k++) s += x[k];
    #pragma unroll
    for (int o = 16; o > 0; o >>= 1) s += __shfl_xor_sync(0xffffffffu, s, o);
    float mu = s * (1.f / 256.f);
    float v = 0.f;
    #pragma unroll
    for (int k = 0; k < 8; k++) { float d = x[k] - mu; v += d * d; }
    #pragma unroll
    for (int o = 16; o > 0; o >>= 1) v += __shfl_xor_sync(0xffffffffu, v, o);
    float rs = rsqrtf(v * (1.f / 256.f) + 1e-6f);

    float y[8];
    #pragma unroll
    for (int k = 0; k < 8; k++)
        y[k] = (x[k] - mu) * rs * lw[cb + k] + lb[cb + k];
    float4 o0, o1;
    o0.x = y[0]; o0.y = y[1]; o0.z = y[2]; o0.w = y[3];
    o1.x = y[4]; o1.y = y[5]; o1.z = y[6]; o1.w = y[7];
    *(float4*)(out + (size_t)row * DM_ + cb)     = o0;
    *(float4*)(out + (size_t)row * DM_ + cb + 4) = o1;
}

// ---------------------------------------------------------------------------
extern "C" void kernel_launch(void* const* d_in, const int* in_sizes, int n_in,
                              void* d_out, int out_size)
{
    const float* hs  = (const float*)d_in[0];
    const float* rpe = (const float*)d_in[1];
    const float* wq  = (const float*)d_in[2];
    const float* wk  = (const float*)d_in[3];
    const float* wv  = (const float*)d_in[4];
    const float* fw  = (const float*)d_in[5];
    const float* fb  = (const float*)d_in[6];
    const float* lw  = (const float*)d_in[7];
    const float* lb  = (const float*)d_in[8];
    const int*   sn  = (const int*)  d_in[9];
    float* out = (float*)d_out;

    cudaFuncSetAttribute(attn_k, cudaFuncAttributeMaxDynamicSharedMemorySize, SMEM_BYTES);

    qkv_k<<<dim3(4, 16, 3), 256>>>(hs, wq, wk, wv);
    attn_k<<<dim3(128, 2), 256, SMEM_BYTES>>>(rpe, sn);
    epi_k<<<128, 256>>>(hs, fw, fb, lw, lb, out);
}

// round 6
// speedup vs baseline: 1.9969x; 1.9969x over previous
#include <cuda_runtime.h>
#include <cstdint>
#include <cstddef>

typedef unsigned long long ull;
#define DI __device__ __forceinline__

DI ull pack2(float x, float y){ ull r; asm("mov.b64 %0,{%1,%2};":"=l"(r):"f"(x),"f"(y)); return r; }
DI float2 unp2(ull v){ float2 r; asm("mov.b64 {%0,%1},%2;":"=f"(r.x),"=f"(r.y):"l"(v)); return r; }
DI ull fma2(ull a, ull b, ull c){ ull d; asm("fma.rn.f32x2 %0,%1,%2,%3;":"=l"(d):"l"(a),"l"(b),"l"(c)); return d; }
DI ull mul2(ull a, ull b){ ull d; asm("mul.rn.f32x2 %0,%1,%2;":"=l"(d):"l"(a),"l"(b)); return d; }

DI void cpa16(void* dst_smem, const void* src_gmem){
    uint32_t s = (uint32_t)__cvta_generic_to_shared(dst_smem);
    asm volatile("cp.async.ca.shared.global [%0], [%1], 16;\n" :: "r"(s), "l"(src_gmem) : "memory");
}
DI void cpa_commit(){ asm volatile("cp.async.commit_group;\n" ::: "memory"); }
template<int N> DI void cpa_wait(){ asm volatile("cp.async.wait_group %0;\n" :: "n"(N) : "memory"); }

constexpr int B_ = 2, S_ = 512, H_ = 8, D_ = 32, DM_ = 256;
constexpr int M_ = B_ * S_;   // 1024 token rows

// Scratch (cudaMalloc forbidden)
__device__ float g_q [M_ * DM_];
__device__ float g_k [M_ * DM_];
__device__ float g_v [M_ * DM_];
__device__ float g_ao[M_ * DM_];

// ---------------------------------------------------------------------------
// Kernel 1: QKV projections. out[m][n] = sum_k x[m][k] * w[k][n]
// 64x64 tiles, K-step 32, cp.async double-buffered. grid (4,16,3), 256 thr.
// ---------------------------------------------------------------------------
__global__ void __launch_bounds__(256) qkv_k(const float* __restrict__ x,
                                             const float* __restrict__ wq,
                                             const float* __restrict__ wk,
                                             const float* __restrict__ wv)
{
    __shared__ float As[2][64][36];   // [buf][m][k] padded row (144B)
    __shared__ float Bs[2][32][64];   // [buf][k][n]
    const int bz = blockIdx.z;
    const float* w = (bz == 0) ? wq : ((bz == 1) ? wk : wv);
    float* out = (bz == 0) ? g_q : ((bz == 1) ? g_k : g_v);
    const int m0 = blockIdx.y * 64, n0 = blockIdx.x * 64;
    const int tid = threadIdx.x, tx = tid & 15, ty = tid >> 4;

    auto stage = [&](int kt){
        int buf = kt & 1, k0 = kt * 32;
        #pragma unroll
        for (int r = 0; r < 2; r++) {            // A: 64x32 -> 512 16B chunks
            int f = r * 256 + tid; int row = f >> 3, kq = f & 7;
            cpa16(&As[buf][row][kq * 4], x + (size_t)(m0 + row) * DM_ + k0 + kq * 4);
        }
        #pragma unroll
        for (int r = 0; r < 2; r++) {            // B: 32x64 -> 512 chunks
            int f = r * 256 + tid; int kk = f >> 4, nq = f & 15;
            cpa16(&Bs[buf][kk][nq * 4], w + (size_t)(k0 + kk) * DM_ + n0 + nq * 4);
        }
    };

    ull acc[4][2];
    #pragma unroll
    for (int r = 0; r < 4; r++) { acc[r][0] = 0ull; acc[r][1] = 0ull; }

    stage(0); cpa_commit();
    stage(1); cpa_commit();

    for (int kt = 0; kt < 8; kt++) {
        if (kt < 7) cpa_wait<1>(); else cpa_wait<0>();
        __syncthreads();
        const int buf = kt & 1;
        #pragma unroll
        for (int k4 = 0; k4 < 8; k4++) {
            ulonglong2 b2[4];
            #pragma unroll
            for (int kk = 0; kk < 4; kk++)
                b2[kk] = *(const ulonglong2*)&Bs[buf][k4 * 4 + kk][tx * 4];
            #pragma unroll
            for (int r = 0; r < 4; r++) {
                float4 a4 = *(const float4*)&As[buf][ty * 4 + r][k4 * 4];
                acc[r][0] = fma2(pack2(a4.x, a4.x), b2[0].x, acc[r][0]);
                acc[r][1] = fma2(pack2(a4.x, a4.x), b2[0].y, acc[r][1]);
                acc[r][0] = fma2(pack2(a4.y, a4.y), b2[1].x, acc[r][0]);
                acc[r][1] = fma2(pack2(a4.y, a4.y), b2[1].y, acc[r][1]);
                acc[r][0] = fma2(pack2(a4.z, a4.z), b2[2].x, acc[r][0]);
                acc[r][1] = fma2(pack2(a4.z, a4.z), b2[2].y, acc[r][1]);
                acc[r][0] = fma2(pack2(a4.w, a4.w), b2[3].x, acc[r][0]);
                acc[r][1] = fma2(pack2(a4.w, a4.w), b2[3].y, acc[r][1]);
            }
        }
        __syncthreads();
        if (kt + 2 < 8) { stage(kt + 2); cpa_commit(); }
    }
    #pragma unroll
    for (int r = 0; r < 4; r++) {
        float2 lo = unp2(acc[r][0]), hi = unp2(acc[r][1]);
        float4 o; o.x = lo.x; o.y = lo.y; o.z = hi.x; o.w = hi.y;
        *(float4*)(out + (size_t)(m0 + ty * 4 + r) * DM_ + n0 + tx * 4) = o;
    }
}

// ---------------------------------------------------------------------------
// Kernel 2: attention. Block = (b, 4 query rows i, all 8 heads). 256 threads.
// scores[b,h,i,j] = sum_d q[b,h,j,d] * k[b,h,i,d] * rpe[b,i,j,d] / sqrt(D)
// mask: j < station_num OR j == i; softmax over j; out = attn @ v.
// j-tiles of 16, all staging in natural layout via cp.async, double-buffered.
// ---------------------------------------------------------------------------
constexpr int JT = 16;
constexpr int QSTR = 260;                             // q/v row stride (floats)
constexpr int OFF_QS = 0;                             // 2 x 16 x 260 = 8320
constexpr int QS_BUF = JT * QSTR;                     // 4160
constexpr int OFF_RP = OFF_QS + 2 * QS_BUF;           // 2 x 4x16x36 = 4608
constexpr int RP_BUF = 4 * JT * 36;                   // 2304
constexpr int OFF_KS = OFF_RP + 2 * RP_BUF;           // 4 x 260 = 1040
constexpr int OFF_SC = OFF_KS + 4 * QSTR;             // 32 x 258 = 8256
constexpr int A_SMEM_FLOATS = OFF_SC + 32 * 258;      // 22224
constexpr int A_SMEM_BYTES  = A_SMEM_FLOATS * 4;      // 88,896 B -> 2 CTAs/SM

__global__ void __launch_bounds__(256, 2) attn_k(const float* __restrict__ rpe,
                                                 const int* __restrict__ snp)
{
    extern __shared__ float sm[];
    float* sc = sm + OFF_SC;
    float* ks = sm + OFF_KS;
    const int tid = threadIdx.x;
    const int b = blockIdx.y, i0 = blockIdx.x * 4;
    int sn = *snp; if (sn > 256) sn = 256; if (sn < 0) sn = 0;
    const int nt = (sn + JT - 1) / JT;                // j-tiles (<=16)
    const float scale = 0.17677669529663687f;         // 1/sqrt(32)

    const int jl = tid & 15, h = (tid >> 4) & 7, ihalf = tid >> 7;
    const int c0 = h * 32;
    const int ig0 = ihalf * 2, ig1 = ihalf * 2 + 1;

    auto stage_row16 = [&](const float* src_base, int t){   // q or v tile
        int buf = t & 1, j0 = t * JT;
        #pragma unroll
        for (int r = 0; r < 4; r++) {
            int f = r * 256 + tid; int row = f >> 6, cq = f & 63;
            cpa16(sm + OFF_QS + buf * QS_BUF + row * QSTR + cq * 4,
                  src_base + (size_t)(b * S_ + j0 + row) * DM_ + cq * 4);
        }
    };
    auto stage_rpe = [&](int t){
        int buf = t & 1, j0 = t * JT;
        #pragma unroll
        for (int r = 0; r < 2; r++) {
            int f = r * 256 + tid; int i = f >> 7, j = (f >> 3) & 15, dq = f & 7;
            cpa16(sm + OFF_RP + buf * RP_BUF + (i * JT + j) * 36 + dq * 4,
                  rpe + ((size_t)(b * S_ + i0 + i) * S_ + j0 + j) * D_ + dq * 4);
        }
    };

    // prologue: k rows (once) + tiles 0,1
    { int row = tid >> 6, cq = tid & 63;                   // 4x256 = 256 chunks
      cpa16(ks + row * QSTR + cq * 4,
            g_k + (size_t)(b * S_ + i0 + row) * DM_ + cq * 4); }
    if (nt > 0) { stage_row16(g_q, 0); stage_rpe(0); }
    cpa_commit();
    if (nt > 1) { stage_row16(g_q, 1); stage_rpe(1); cpa_commit(); }
    if (nt == 0) { cpa_wait<0>(); __syncthreads(); }

    // ---------------- score phase ----------------
    for (int t = 0; t < nt; t++) {
        if (t + 1 < nt) cpa_wait<1>(); else cpa_wait<0>();
        __syncthreads();
        const int buf = t & 1, j0 = t * JT;
        const float* qrow = sm + OFF_QS + buf * QS_BUF + jl * QSTR + c0;
        const float* rb   = sm + OFF_RP + buf * RP_BUF;
        ull a0 = 0ull, a1 = 0ull;
        #pragma unroll
        for (int d4 = 0; d4 < 8; d4++) {
            ulonglong2 q2 = *(const ulonglong2*)(qrow + d4 * 4);
            ulonglong2 r0 = *(const ulonglong2*)(rb + (ig0 * JT + jl) * 36 + d4 * 4);
            ulonglong2 k0 = *(const ulonglong2*)(ks + ig0 * QSTR + c0 + d4 * 4);
            a0 = fma2(mul2(q2.x, k0.x), r0.x, a0);
            a0 = fma2(mul2(q2.y, k0.y), r0.y, a0);
            ulonglong2 r1 = *(const ulonglong2*)(rb + (ig1 * JT + jl) * 36 + d4 * 4);
            ulonglong2 k1 = *(const ulonglong2*)(ks + ig1 * QSTR + c0 + d4 * 4);
            a1 = fma2(mul2(q2.x, k1.x), r1.x, a1);
            a1 = fma2(mul2(q2.y, k1.y), r1.y, a1);
        }
        int jg = j0 + jl;
        if (jg < sn) {
            float2 t0 = unp2(a0), t1 = unp2(a1);
            sc[(ig0 * 8 + h) * 258 + jg] = (t0.x + t0.y) * scale;
            sc[(ig1 * 8 + h) * 258 + jg] = (t1.x + t1.y) * scale;
        }
        __syncthreads();
        if (t + 2 < nt) { stage_row16(g_q, t + 2); stage_rpe(t + 2); cpa_commit(); }
    }

    // prefetch v tiles 0,1 (overlaps diag + softmax)
    if (nt > 0) { stage_row16(g_v, 0); cpa_commit(); }
    if (nt > 1) { stage_row16(g_v, 1); cpa_commit(); }

    // diagonal column (only matters when i >= sn)
    if (tid < 32) {
        int il = tid >> 3, hh = tid & 7, i = i0 + il;
        if (i >= sn) {
            float s = 0.f;
            const float* qrow = g_q + (size_t)(b * S_ + i) * DM_ + hh * 32;
            const float* rrow = rpe + ((size_t)(b * S_ + i) * S_ + i) * D_;
            #pragma unroll
            for (int d = 0; d < 32; d++)
                s += qrow[d] * ks[il * QSTR + hh * 32 + d] * rrow[d];
            sc[(il * 8 + hh) * 258 + 256] = s * scale;
        }
    }
    __syncthreads();

    // ---------------- softmax (8 warps x 4 rows) ----------------
    {
        int w = tid >> 5, lane = tid & 31;
        int jmax = nt * JT;
        for (int rr = 0; rr < 4; rr++) {
            int row = w * 4 + rr; int il = row >> 3, hh = row & 7;
            bool hd = (i0 + il) >= sn;
            float* srow = &sc[(il * 8 + hh) * 258];
            float mx = -1e30f;
            for (int jj = lane; jj < sn; jj += 32) mx = fmaxf(mx, srow[jj]);
            if (hd && lane == 0) mx = fmaxf(mx, srow[256]);
            #pragma unroll
            for (int o = 16; o > 0; o >>= 1) mx = fmaxf(mx, __shfl_xor_sync(0xffffffffu, mx, o));
            float sum = 0.f;
            for (int jj = lane; jj < jmax; jj += 32) {
                float p = (jj < sn) ? __expf(srow[jj] - mx) : 0.f;
                srow[jj] = p; sum += p;
            }
            if (hd && lane == 0) { float p = __expf(srow[256] - mx); srow[256] = p; sum += p; }
            #pragma unroll
            for (int o = 16; o > 0; o >>= 1) sum += __shfl_xor_sync(0xffffffffu, sum, o);
            float rn = 1.f / sum;
            for (int jj = lane; jj < jmax; jj += 32) srow[jj] *= rn;
            if (hd && lane == 0) srow[256] *= rn;
        }
    }

    // ---------------- AV phase ----------------
    const int dp = jl;   // col-pair within head: cols c0+2dp, c0+2dp+1
    ull av0 = 0ull, av1 = 0ull;
    for (int t = 0; t < nt; t++) {
        if (t + 1 < nt) cpa_wait<1>(); else cpa_wait<0>();
        __syncthreads();
        const int buf = t & 1, j0 = t * JT;
        const float* vb = sm + OFF_QS + buf * QS_BUF;
        #pragma unroll
        for (int j = 0; j < JT; j++) {
            int jg = j0 + j;
            ull v2 = *(const ull*)(vb + j * QSTR + c0 + 2 * dp);
            float p0 = sc[(ig0 * 8 + h) * 258 + jg];
            av0 = fma2(pack2(p0, p0), v2, av0);
            float p1 = sc[(ig1 * 8 + h) * 258 + jg];
            av1 = fma2(pack2(p1, p1), v2, av1);
        }
        __syncthreads();
        if (t + 2 < nt) { stage_row16(g_v, t + 2); cpa_commit(); }
    }
    // diagonal contribution + store
    {
        int ig = i0 + ig0;
        if (ig >= sn) {
            float p = sc[(ig0 * 8 + h) * 258 + 256];
            float2 vv = *(const float2*)(g_v + (size_t)(b * S_ + ig) * DM_ + c0 + 2 * dp);
            av0 = fma2(pack2(p, p), pack2(vv.x, vv.y), av0);
        }
        float2 o = unp2(av0);
        *(float2*)(g_ao + (size_t)(b * S_ + ig) * DM_ + c0 + 2 * dp) = o;
    }
    {
        int ig = i0 + ig1;
        if (ig >= sn) {
            float p = sc[(ig1 * 8 + h) * 258 + 256];
            float2 vv = *(const float2*)(g_v + (size_t)(b * S_ + ig) * DM_ + c0 + 2 * dp);
            av1 = fma2(pack2(p, p), pack2(vv.x, vv.y), av1);
        }
        float2 o = unp2(av1);
        *(float2*)(g_ao + (size_t)(b * S_ + ig) * DM_ + c0 + 2 * dp) = o;
    }
}

// ---------------------------------------------------------------------------
// Kernel 3: epilogue. ctx = ao @ fc_w + fc_b + hs, then layernorm.
// Block = 8 rows x 256 cols; fc_w staged through smem in 32-k chunks
// (double-buffered cp.async). 128 blocks x 256 threads.
// ---------------------------------------------------------------------------
constexpr int EOFF_AO  = 0;                      // 8 x 260 = 2080
constexpr int EOFF_WS  = 2080;                   // 2 x 32 x 260 = 16640
constexpr int EWS_BUF  = 32 * 260;               // 8320
constexpr int EOFF_CTX = EOFF_WS + 2 * EWS_BUF;  // 8 x 260 = 2080
constexpr int E_SMEM_FLOATS = EOFF_CTX + 8 * 260;    // 20800
constexpr int E_SMEM_BYTES  = E_SMEM_FLOATS * 4;     // 83,200 B

__global__ void __launch_bounds__(256) epi_k(const float* __restrict__ hs,
                                             const float* __restrict__ fw,
                                             const float* __restrict__ fb,
                                             const float* __restrict__ lw,
                                             const float* __restrict__ lb,
                                             float* __restrict__ out)
{
    extern __shared__ float es[];
    float* aos = es + EOFF_AO;
    float* ctx = es + EOFF_CTX;
    const int tid = threadIdx.x;
    const int cp = tid & 127, rh = tid >> 7;     // col-pair, row-half
    const int row0 = blockIdx.x * 8;

    auto stage_w = [&](int kt){
        int buf = kt & 1, k0 = kt * 32;
        #pragma unroll
        for (int r = 0; r < 8; r++) {            // 32x256 -> 2048 chunks
            int f = r * 256 + tid; int kr = f >> 6, cq = f & 63;
            cpa16(es + EOFF_WS + buf * EWS_BUF + kr * 260 + cq * 4,
                  fw + (size_t)(k0 + kr) * DM_ + cq * 4);
        }
    };
    // stage ao rows (group 0 with W chunk 0)
    #pragma unroll
    for (int r = 0; r < 2; r++) {
        int f = r * 256 + tid; int row = f >> 6, cq = f & 63;
        cpa16(aos + row * 260 + cq * 4, g_ao + (size_t)(row0 + row) * DM_ + cq * 4);
    }
    stage_w(0); cpa_commit();
    stage_w(1); cpa_commit();

    ull acc[4] = {0ull, 0ull, 0ull, 0ull};
    for (int kt = 0; kt < 8; kt++) {
        if (kt < 7) cpa_wait<1>(); else cpa_wait<0>();
        __syncthreads();
        const float* wb = es + EOFF_WS + (kt & 1) * EWS_BUF;
        const int k0 = kt * 32;
        #pragma unroll 8
        for (int kk = 0; kk < 32; kk++) {
            ull w2 = *(const ull*)(wb + kk * 260 + 2 * cp);
            #pragma unroll
            for (int r = 0; r < 4; r++) {
                float a = aos[(rh * 4 + r) * 260 + k0 + kk];
                acc[r] = fma2(pack2(a, a), w2, acc[r]);
            }
        }
        __syncthreads();
        if (kt + 2 < 8) { stage_w(kt + 2); cpa_commit(); }
    }

    // bias + residual, write ctx tile
    const int cb = 2 * cp;
    float2 fb2 = *(const float2*)(fb + cb);
    #pragma unroll
    for (int r = 0; r < 4; r++) {
        int row = row0 + rh * 4 + r;
        float2 h2 = *(const float2*)(hs + (size_t)row * DM_ + cb);
        float2 t = unp2(acc[r]);
        t.x += fb2.x + h2.x; t.y += fb2.y + h2.y;
        *(float2*)(ctx + (rh * 4 + r) * 260 + cb) = t;
    }
    __syncthreads();

    // layernorm: warp per row
    {
        int w = tid >> 5, lane = tid & 31;
        float4 x0 = *(const float4*)(ctx + w * 260 + lane * 8);
        float4 x1 = *(const float4*)(ctx + w * 260 + lane * 8 + 4);
        float s = x0.x + x0.y + x0.z + x0.w + x1.x + x1.y + x1.z + x1.w;
        #pragma unroll
        for (int o = 16; o > 0; o >>= 1) s += __shfl_xor_sync(0xffffffffu, s, o);
        float mu = s * (1.f / 256.f);
        float v = 0.f;
        float xs[8] = {x0.x, x0.y, x0.z, x0.w, x1.x, x1.y, x1.z, x1.w};
        #pragma unroll
        for (int k = 0; k < 8; k++) { float d = xs[k] - mu; v += d * d; }
        #pragma unroll
        for (int o = 16; o > 0; o >>= 1) v += __shfl_xor_sync(0xffffffffu, v, o);
        float rs = rsqrtf(v * (1.f / 256.f) + 1e-6f);
        int c = lane * 8;
        float4 lw0 = *(const float4*)(lw + c), lw1 = *(const float4*)(lw + c + 4);
        float4 lb0 = *(const float4*)(lb + c), lb1 = *(const float4*)(lb + c + 4);
        float4 y0, y1;
        y0.x = (xs[0]-mu)*rs*lw0.x + lb0.x; y0.y = (xs[1]-mu)*rs*lw0.y + lb0.y;
        y0.z = (xs[2]-mu)*rs*lw0.z + lb0.z; y0.w = (xs[3]-mu)*rs*lw0.w + lb0.w;
        y1.x = (xs[4]-mu)*rs*lw1.x + lb1.x; y1.y = (xs[5]-mu)*rs*lw1.y + lb1.y;
        y1.z = (xs[6]-mu)*rs*lw1.z + lb1.z; y1.w = (xs[7]-mu)*rs*lw1.w + lb1.w;
        size_t ro = (size_t)(row0 + w) * DM_ + c;
        *(float4*)(out + ro)     = y0;
        *(float4*)(out + ro + 4) = y1;
    }
}

// ---------------------------------------------------------------------------
extern "C" void kernel_launch(void* const* d_in, const int* in_sizes, int n_in,
                              void* d_out, int out_size)
{
    const float* hs  = (const float*)d_in[0];
    const float* rpe = (const float*)d_in[1];
    const float* wq  = (const float*)d_in[2];
    const float* wk  = (const float*)d_in[3];
    const float* wv  = (const float*)d_in[4];
    const float* fw  = (const float*)d_in[5];
    const float* fb  = (const float*)d_in[6];
    const float* lw  = (const float*)d_in[7];
    const float* lb  = (const float*)d_in[8];
    const int*   sn  = (const int*)  d_in[9];
    float* out = (float*)d_out;

    cudaFuncSetAttribute(attn_k, cudaFuncAttributeMaxDynamicSharedMemorySize, A_SMEM_BYTES);
    cudaFuncSetAttribute(epi_k,  cudaFuncAttributeMaxDynamicSharedMemorySize, E_SMEM_BYTES);

    qkv_k<<<dim3(4, 16, 3), 256>>>(hs, wq, wk, wv);
    attn_k<<<dim3(128, 2), 256, A_SMEM_BYTES>>>(rpe, sn);
    epi_k<<<128, 256, E_SMEM_BYTES>>>(hs, fw, fb, lw, lb, out);
}